// round 3
// baseline (speedup 1.0000x reference)
#include <cuda_runtime.h>
#include <cuda_bf16.h>
#include <cstdint>
#include <cstddef>

// ---------------------------------------------------------------------------
// Problem constants
// ---------------------------------------------------------------------------
static constexpr int D_DIM  = 2496;   // 16*13*12
static constexpr int B_ROWS = 4096;
static constexpr int S_ROWS = 2048;
static constexpr float OUT_SCALE = -1.0f / 500.0f;

// GEMM tiling (legacy mma.sync path — tcgen05 not available on this build's
// PTX target sm_103 (non-'a'))
static constexpr int BM = 128;            // batch rows per CTA (M)
static constexpr int BN = 256;            // states per CTA (N)
static constexpr int BK = 32;             // K per stage
static constexpr int KITERS = D_DIM / BK; // 78 exact
static constexpr int STAGES = 4;

// Padded smem rows: 32 bf16 = 64 B data + 16 B pad = 80 B stride.
// Bank math: 80 B = 20 words; start banks of 8 consecutive rows are
// {0,20,8,28,16,4,24,12} -> conflict-free for 16B-chunk accesses.
static constexpr int ROW_STRIDE  = 80;
static constexpr int A_ST_BYTES  = BM * ROW_STRIDE;          // 10240
static constexpr int B_ST_BYTES  = BN * ROW_STRIDE;          // 20480
static constexpr int STAGE_BYTES = A_ST_BYTES + B_ST_BYTES;  // 30720
static constexpr int OFF_STATS   = STAGES * STAGE_BYTES;     // 122880
static constexpr int SMEM_BYTES  = OFF_STATS + (BM + BN) * 4; // 124416

// ---------------------------------------------------------------------------
// Device scratch (allocation-free rule: __device__ globals)
// ---------------------------------------------------------------------------
__device__ __align__(128) __nv_bfloat16 g_Xbf[(size_t)B_ROWS * D_DIM];
__device__ __align__(128) __nv_bfloat16 g_Mbf[(size_t)S_ROWS * D_DIM];
__device__ float g_xsq[B_ROWS];
__device__ float g_msq[S_ROWS];

// ---------------------------------------------------------------------------
// Helpers
// ---------------------------------------------------------------------------
__device__ __forceinline__ uint32_t smem_u32(const void* p) {
    uint32_t a;
    asm("{ .reg .u64 t; cvta.to.shared.u64 t, %1; cvt.u32.u64 %0, t; }"
        : "=r"(a) : "l"(p));
    return a;
}

__device__ __forceinline__ void cp_async16(uint32_t dst, const void* src) {
    asm volatile("cp.async.cg.shared.global [%0], [%1], 16;" :: "r"(dst), "l"(src));
}

__device__ __forceinline__ void ldmat_x4(uint32_t* r, uint32_t addr) {
    asm volatile("ldmatrix.sync.aligned.m8n8.x4.shared.b16 {%0,%1,%2,%3}, [%4];"
                 : "=r"(r[0]), "=r"(r[1]), "=r"(r[2]), "=r"(r[3]) : "r"(addr));
}

__device__ __forceinline__ void ldmat_x2(uint32_t* r, uint32_t addr) {
    asm volatile("ldmatrix.sync.aligned.m8n8.x2.shared.b16 {%0,%1}, [%2];"
                 : "=r"(r[0]), "=r"(r[1]) : "r"(addr));
}

__device__ __forceinline__ void mma_bf16(float* c, const uint32_t* a, const uint32_t* b) {
    asm volatile(
        "mma.sync.aligned.m16n8k16.row.col.f32.bf16.bf16.f32 "
        "{%0,%1,%2,%3}, {%4,%5,%6,%7}, {%8,%9}, {%0,%1,%2,%3};"
        : "+f"(c[0]), "+f"(c[1]), "+f"(c[2]), "+f"(c[3])
        : "r"(a[0]), "r"(a[1]), "r"(a[2]), "r"(a[3]), "r"(b[0]), "r"(b[1]));
}

// ---------------------------------------------------------------------------
// Stage loader: A tile 128x32 bf16, B tile 256x32 bf16 via cp.async (16B)
// ---------------------------------------------------------------------------
__device__ __forceinline__ void load_stage(uint32_t sbase,
                                           const __nv_bfloat16* __restrict__ Xt,
                                           const __nv_bfloat16* __restrict__ Mt,
                                           int tid) {
#pragma unroll
    for (int i = 0; i < 2; i++) {                     // A: 512 chunks
        int idx = i * 256 + tid;
        int row = idx >> 2, ch = idx & 3;
        cp_async16(sbase + row * ROW_STRIDE + ch * 16,
                   Xt + (size_t)row * D_DIM + ch * 8);
    }
#pragma unroll
    for (int i = 0; i < 4; i++) {                     // B: 1024 chunks
        int idx = i * 256 + tid;
        int row = idx >> 2, ch = idx & 3;
        cp_async16(sbase + A_ST_BYTES + row * ROW_STRIDE + ch * 16,
                   Mt + (size_t)row * D_DIM + ch * 8);
    }
}

// ---------------------------------------------------------------------------
// Conversion: fp32 -> bf16 + exact fp32 row sum-of-squares
// ---------------------------------------------------------------------------
__global__ void __launch_bounds__(256)
convert_kernel(const float* __restrict__ src, __nv_bfloat16* __restrict__ dst,
               float* __restrict__ sq) {
    int row = blockIdx.x;
    const float* s = src + (size_t)row * D_DIM;
    __nv_bfloat16* d = dst + (size_t)row * D_DIM;
    float acc = 0.f;
    for (int i = threadIdx.x; i < D_DIM; i += 256) {
        float v = s[i];
        acc = fmaf(v, v, acc);
        d[i] = __float2bfloat16(v);
    }
#pragma unroll
    for (int o = 16; o > 0; o >>= 1) acc += __shfl_xor_sync(0xffffffffu, acc, o);
    __shared__ float wsum[8];
    if ((threadIdx.x & 31) == 0) wsum[threadIdx.x >> 5] = acc;
    __syncthreads();
    if (threadIdx.x == 0) {
        float t = 0.f;
#pragma unroll
        for (int i = 0; i < 8; i++) t += wsum[i];
        sq[row] = t;
    }
}

// ---------------------------------------------------------------------------
// GEMM + fused epilogue: out[b,s] = (xsq[b] + msq[s] - 2*cross) * (-1/500)
// 256 threads = 8 warps in 2(M) x 4(N); warp tile 64x64.
// ---------------------------------------------------------------------------
__global__ void __launch_bounds__(256)
gemm_kernel(float* __restrict__ out) {
    extern __shared__ char smem[];
    const uint32_t smem_base = smem_u32(smem);
    const int tid    = threadIdx.x;
    const int wid    = tid >> 5;
    const int lane   = tid & 31;
    const int warp_m = wid >> 2;          // 0..1
    const int warp_n = wid & 3;           // 0..3
    const int bn     = blockIdx.x;        // 0..7
    const int bm     = blockIdx.y;        // 0..31

    // Stage row norms into smem (overlaps with cp.async prologue)
    float* xs_s = (float*)(smem + OFF_STATS);
    float* ms_s = xs_s + BM;
    if (tid < BM) xs_s[tid] = g_xsq[bm * BM + tid];
    ms_s[tid] = g_msq[bn * BN + tid];     // BN == 256 == blockDim

    const __nv_bfloat16* Xbase = g_Xbf + (size_t)(bm * BM) * D_DIM;
    const __nv_bfloat16* Mbase = g_Mbf + (size_t)(bn * BN) * D_DIM;

    // Prologue: fill STAGES-1 stages
#pragma unroll
    for (int s = 0; s < STAGES - 1; s++) {
        load_stage(smem_base + s * STAGE_BYTES,
                   Xbase + (size_t)s * BK, Mbase + (size_t)s * BK, tid);
        asm volatile("cp.async.commit_group;" ::: "memory");
    }

    float acc[4][8][4];
#pragma unroll
    for (int t = 0; t < 4; t++)
#pragma unroll
        for (int u = 0; u < 8; u++)
#pragma unroll
            for (int j = 0; j < 4; j++) acc[t][u][j] = 0.f;

    // Per-lane ldmatrix address components (stage-invariant parts)
    const int a_row = warp_m * 64 + (lane & 15);
    const int a_sel = (lane >> 4) * 16;               // +8 cols for mats 2,3
    const int b_row = warp_n * 64 + (lane & 7);
    const int b_sel = ((lane >> 3) & 1) * 16;         // k lo/hi 8

#pragma unroll 1
    for (int kk = 0; kk < KITERS; kk++) {
        asm volatile("cp.async.wait_group 2;" ::: "memory");
        __syncthreads();

        // Prefetch stage kk+3 into slot (kk+3)&3 (computed at iter kk-1; safe
        // after the barrier above).
        int kn = kk + STAGES - 1;
        if (kn < KITERS) {
            load_stage(smem_base + (kn & 3) * STAGE_BYTES,
                       Xbase + (size_t)kn * BK, Mbase + (size_t)kn * BK, tid);
        }
        asm volatile("cp.async.commit_group;" ::: "memory");

        const uint32_t sA = smem_base + (kk & 3) * STAGE_BYTES;
        const uint32_t sB = sA + A_ST_BYTES;

#pragma unroll
        for (int ks = 0; ks < 2; ks++) {              // two k16 steps per BK=32
            const int koff = ks * 32;                 // bytes
            uint32_t a[4][4], b[8][2];
#pragma unroll
            for (int t = 0; t < 4; t++)
                ldmat_x4(a[t], sA + (a_row + t * 16) * ROW_STRIDE + koff + a_sel);
#pragma unroll
            for (int u = 0; u < 8; u++)
                ldmat_x2(b[u], sB + (b_row + u * 8) * ROW_STRIDE + koff + b_sel);
#pragma unroll
            for (int t = 0; t < 4; t++)
#pragma unroll
                for (int u = 0; u < 8; u++)
                    mma_bf16(acc[t][u], a[t], b[u]);
        }
    }

    // ---------------- Epilogue ----------------
    const int g  = lane >> 2;
    const int tg = lane & 3;
    const int mloc = warp_m * 64;
    const int nloc = warp_n * 64;

#pragma unroll
    for (int t = 0; t < 4; t++) {
        const int r0 = mloc + t * 16 + g;
        const float xsa = xs_s[r0];
        const float xsb = xs_s[r0 + 8];
        float* o0 = out + (size_t)(bm * BM + r0) * S_ROWS + bn * BN;
        float* o1 = o0 + (size_t)8 * S_ROWS;
#pragma unroll
        for (int u = 0; u < 8; u++) {
            const int col = nloc + u * 8 + tg * 2;
            const float m0 = ms_s[col], m1 = ms_s[col + 1];
            float2 v0, v1;
            v0.x = (xsa + m0 - 2.f * acc[t][u][0]) * OUT_SCALE;
            v0.y = (xsa + m1 - 2.f * acc[t][u][1]) * OUT_SCALE;
            v1.x = (xsb + m0 - 2.f * acc[t][u][2]) * OUT_SCALE;
            v1.y = (xsb + m1 - 2.f * acc[t][u][3]) * OUT_SCALE;
            *(float2*)(o0 + col) = v0;
            *(float2*)(o1 + col) = v1;
        }
    }
}

// ---------------------------------------------------------------------------
// Launch
// ---------------------------------------------------------------------------
extern "C" void kernel_launch(void* const* d_in, const int* in_sizes, int n_in,
                              void* d_out, int out_size) {
    (void)n_in; (void)out_size;
    const float* X = (const float*)d_in[0];   // observation        [4096, 2496]
    const float* M = (const float*)d_in[1];   // observation_matrix [2048, 2496]
    if (in_sizes[0] == S_ROWS * D_DIM) {      // robust to ordering
        X = (const float*)d_in[1];
        M = (const float*)d_in[0];
    }
    float* out = (float*)d_out;

    cudaFuncSetAttribute(gemm_kernel,
                         cudaFuncAttributeMaxDynamicSharedMemorySize, SMEM_BYTES);

    __nv_bfloat16 *xbf = nullptr, *mbf = nullptr;
    float *xsq = nullptr, *msq = nullptr;
    cudaGetSymbolAddress((void**)&xbf, g_Xbf);
    cudaGetSymbolAddress((void**)&mbf, g_Mbf);
    cudaGetSymbolAddress((void**)&xsq, g_xsq);
    cudaGetSymbolAddress((void**)&msq, g_msq);

    convert_kernel<<<B_ROWS, 256>>>(X, xbf, xsq);
    convert_kernel<<<S_ROWS, 256>>>(M, mbf, msq);

    dim3 grid(S_ROWS / BN, B_ROWS / BM);  // (8, 32) = 256 CTAs
    gemm_kernel<<<grid, 256, SMEM_BYTES>>>(out);
}

// round 4
// speedup vs baseline: 1.1144x; 1.1144x over previous
#include <cuda_runtime.h>
#include <cuda_bf16.h>
#include <cstdint>
#include <cstddef>

// ---------------------------------------------------------------------------
// Problem constants
// ---------------------------------------------------------------------------
static constexpr int D_DIM  = 2496;   // 16*13*12
static constexpr int B_ROWS = 4096;
static constexpr int S_ROWS = 2048;
static constexpr float OUT_SCALE = -1.0f / 500.0f;

// GEMM tiling (legacy mma.sync path — tcgen05 not available on this build's
// PTX target sm_103 (non-'a'))
static constexpr int BM = 128;            // batch rows per CTA (M)
static constexpr int BN = 256;            // states per CTA (N)
static constexpr int BK = 32;             // K per stage
static constexpr int KITERS = D_DIM / BK; // 78 exact
static constexpr int STAGES = 4;

// Padded smem rows: 32 bf16 = 64 B data + 16 B pad = 80 B stride.
static constexpr int ROW_STRIDE  = 80;
static constexpr int A_ST_BYTES  = BM * ROW_STRIDE;          // 10240
static constexpr int B_ST_BYTES  = BN * ROW_STRIDE;          // 20480
static constexpr int STAGE_BYTES = A_ST_BYTES + B_ST_BYTES;  // 30720
static constexpr int OFF_STATS   = STAGES * STAGE_BYTES;     // 122880
static constexpr int SMEM_BYTES  = OFF_STATS + (BM + BN) * 4; // 124416

// ---------------------------------------------------------------------------
// Device scratch (allocation-free rule: __device__ globals)
// ---------------------------------------------------------------------------
__device__ __align__(128) __nv_bfloat16 g_Xbf[(size_t)B_ROWS * D_DIM];
__device__ __align__(128) __nv_bfloat16 g_Mbf[(size_t)S_ROWS * D_DIM];
__device__ float g_xsq[B_ROWS];
__device__ float g_msq[S_ROWS];

// ---------------------------------------------------------------------------
// Helpers
// ---------------------------------------------------------------------------
__device__ __forceinline__ uint32_t smem_u32(const void* p) {
    uint32_t a;
    asm("{ .reg .u64 t; cvta.to.shared.u64 t, %1; cvt.u32.u64 %0, t; }"
        : "=r"(a) : "l"(p));
    return a;
}

__device__ __forceinline__ void cp_async16(uint32_t dst, const void* src) {
    asm volatile("cp.async.cg.shared.global [%0], [%1], 16;" :: "r"(dst), "l"(src));
}

__device__ __forceinline__ void ldmat_x4(uint32_t* r, uint32_t addr) {
    asm volatile("ldmatrix.sync.aligned.m8n8.x4.shared.b16 {%0,%1,%2,%3}, [%4];"
                 : "=r"(r[0]), "=r"(r[1]), "=r"(r[2]), "=r"(r[3]) : "r"(addr));
}

__device__ __forceinline__ void ldmat_x2(uint32_t* r, uint32_t addr) {
    asm volatile("ldmatrix.sync.aligned.m8n8.x2.shared.b16 {%0,%1}, [%2];"
                 : "=r"(r[0]), "=r"(r[1]) : "r"(addr));
}

__device__ __forceinline__ void mma_bf16(float* c, const uint32_t* a, const uint32_t* b) {
    asm volatile(
        "mma.sync.aligned.m16n8k16.row.col.f32.bf16.bf16.f32 "
        "{%0,%1,%2,%3}, {%4,%5,%6,%7}, {%8,%9}, {%0,%1,%2,%3};"
        : "+f"(c[0]), "+f"(c[1]), "+f"(c[2]), "+f"(c[3])
        : "r"(a[0]), "r"(a[1]), "r"(a[2]), "r"(a[3]), "r"(b[0]), "r"(b[1]));
}

// ---------------------------------------------------------------------------
// Stage loader: A tile 128x32 bf16, B tile 256x32 bf16 via cp.async (16B)
// ---------------------------------------------------------------------------
__device__ __forceinline__ void load_stage(uint32_t sbase,
                                           const __nv_bfloat16* __restrict__ Xt,
                                           const __nv_bfloat16* __restrict__ Mt,
                                           int tid) {
#pragma unroll
    for (int i = 0; i < 2; i++) {                     // A: 512 chunks
        int idx = i * 256 + tid;
        int row = idx >> 2, ch = idx & 3;
        cp_async16(sbase + row * ROW_STRIDE + ch * 16,
                   Xt + (size_t)row * D_DIM + ch * 8);
    }
#pragma unroll
    for (int i = 0; i < 4; i++) {                     // B: 1024 chunks
        int idx = i * 256 + tid;
        int row = idx >> 2, ch = idx & 3;
        cp_async16(sbase + A_ST_BYTES + row * ROW_STRIDE + ch * 16,
                   Mt + (size_t)row * D_DIM + ch * 8);
    }
}

// ---------------------------------------------------------------------------
// Merged, vectorized conversion: fp32 -> bf16 + exact fp32 row sum-of-squares.
// One block per row across BOTH matrices (X rows first, then M rows).
// float4 loads (16 B), packed bf16x4 stores (8 B).
// ---------------------------------------------------------------------------
static constexpr int ROW_F4 = D_DIM / 4;  // 624 float4 per row

__global__ void __launch_bounds__(256)
convert_all_kernel(const float* __restrict__ X, const float* __restrict__ M) {
    const int b = blockIdx.x;
    const bool isX = (b < B_ROWS);
    const int row  = isX ? b : b - B_ROWS;
    const float4* src = (const float4*)((isX ? X : M) + (size_t)row * D_DIM);
    uint2* dst = (uint2*)((isX ? g_Xbf : g_Mbf) + (size_t)row * D_DIM);
    float* sq  = isX ? &g_xsq[row] : &g_msq[row];

    float acc = 0.f;
#pragma unroll 3
    for (int i = threadIdx.x; i < ROW_F4; i += 256) {
        float4 v = src[i];
        acc = fmaf(v.x, v.x, acc);
        acc = fmaf(v.y, v.y, acc);
        acc = fmaf(v.z, v.z, acc);
        acc = fmaf(v.w, v.w, acc);
        __nv_bfloat162 lo = __floats2bfloat162_rn(v.x, v.y);
        __nv_bfloat162 hi = __floats2bfloat162_rn(v.z, v.w);
        uint2 o;
        o.x = *(uint32_t*)&lo;
        o.y = *(uint32_t*)&hi;
        dst[i] = o;
    }
#pragma unroll
    for (int o = 16; o > 0; o >>= 1) acc += __shfl_xor_sync(0xffffffffu, acc, o);
    __shared__ float wsum[8];
    if ((threadIdx.x & 31) == 0) wsum[threadIdx.x >> 5] = acc;
    __syncthreads();
    if (threadIdx.x == 0) {
        float t = 0.f;
#pragma unroll
        for (int i = 0; i < 8; i++) t += wsum[i];
        *sq = t;
    }
}

// ---------------------------------------------------------------------------
// GEMM + fused epilogue: out[b,s] = (xsq[b] + msq[s] - 2*cross) * (-1/500)
// 256 threads = 8 warps in 2(M) x 4(N); warp tile 64x64.
// ---------------------------------------------------------------------------
__global__ void __launch_bounds__(256)
gemm_kernel(float* __restrict__ out) {
    extern __shared__ char smem[];
    const uint32_t smem_base = smem_u32(smem);
    const int tid    = threadIdx.x;
    const int wid    = tid >> 5;
    const int lane   = tid & 31;
    const int warp_m = wid >> 2;          // 0..1
    const int warp_n = wid & 3;           // 0..3
    const int bn     = blockIdx.x;        // 0..7
    const int bm     = blockIdx.y;        // 0..31

    // Stage row norms into smem (overlaps with cp.async prologue)
    float* xs_s = (float*)(smem + OFF_STATS);
    float* ms_s = xs_s + BM;
    if (tid < BM) xs_s[tid] = g_xsq[bm * BM + tid];
    ms_s[tid] = g_msq[bn * BN + tid];     // BN == 256 == blockDim

    const __nv_bfloat16* Xbase = g_Xbf + (size_t)(bm * BM) * D_DIM;
    const __nv_bfloat16* Mbase = g_Mbf + (size_t)(bn * BN) * D_DIM;

    // Prologue: fill STAGES-1 stages
#pragma unroll
    for (int s = 0; s < STAGES - 1; s++) {
        load_stage(smem_base + s * STAGE_BYTES,
                   Xbase + (size_t)s * BK, Mbase + (size_t)s * BK, tid);
        asm volatile("cp.async.commit_group;" ::: "memory");
    }

    float acc[4][8][4];
#pragma unroll
    for (int t = 0; t < 4; t++)
#pragma unroll
        for (int u = 0; u < 8; u++)
#pragma unroll
            for (int j = 0; j < 4; j++) acc[t][u][j] = 0.f;

    // Per-lane ldmatrix address components (stage-invariant parts)
    const int a_row = warp_m * 64 + (lane & 15);
    const int a_sel = (lane >> 4) * 16;               // +8 cols for mats 2,3
    const int b_row = warp_n * 64 + (lane & 7);
    const int b_sel = ((lane >> 3) & 1) * 16;         // k lo/hi 8

#pragma unroll 1
    for (int kk = 0; kk < KITERS; kk++) {
        asm volatile("cp.async.wait_group 2;" ::: "memory");
        __syncthreads();

        // Prefetch stage kk+3 into slot (kk+3)&3
        int kn = kk + STAGES - 1;
        if (kn < KITERS) {
            load_stage(smem_base + (kn & 3) * STAGE_BYTES,
                       Xbase + (size_t)kn * BK, Mbase + (size_t)kn * BK, tid);
        }
        asm volatile("cp.async.commit_group;" ::: "memory");

        const uint32_t sA = smem_base + (kk & 3) * STAGE_BYTES;
        const uint32_t sB = sA + A_ST_BYTES;

#pragma unroll
        for (int ks = 0; ks < 2; ks++) {              // two k16 steps per BK=32
            const int koff = ks * 32;                 // bytes
            uint32_t a[4][4], b[8][2];
#pragma unroll
            for (int t = 0; t < 4; t++)
                ldmat_x4(a[t], sA + (a_row + t * 16) * ROW_STRIDE + koff + a_sel);
#pragma unroll
            for (int u = 0; u < 8; u++)
                ldmat_x2(b[u], sB + (b_row + u * 8) * ROW_STRIDE + koff + b_sel);
#pragma unroll
            for (int t = 0; t < 4; t++)
#pragma unroll
                for (int u = 0; u < 8; u++)
                    mma_bf16(acc[t][u], a[t], b[u]);
        }
    }

    // ---------------- Epilogue ----------------
    const int g  = lane >> 2;
    const int tg = lane & 3;
    const int mloc = warp_m * 64;
    const int nloc = warp_n * 64;

#pragma unroll
    for (int t = 0; t < 4; t++) {
        const int r0 = mloc + t * 16 + g;
        const float xsa = xs_s[r0];
        const float xsb = xs_s[r0 + 8];
        float* o0 = out + (size_t)(bm * BM + r0) * S_ROWS + bn * BN;
        float* o1 = o0 + (size_t)8 * S_ROWS;
#pragma unroll
        for (int u = 0; u < 8; u++) {
            const int col = nloc + u * 8 + tg * 2;
            const float m0 = ms_s[col], m1 = ms_s[col + 1];
            float2 v0, v1;
            v0.x = (xsa + m0 - 2.f * acc[t][u][0]) * OUT_SCALE;
            v0.y = (xsa + m1 - 2.f * acc[t][u][1]) * OUT_SCALE;
            v1.x = (xsb + m0 - 2.f * acc[t][u][2]) * OUT_SCALE;
            v1.y = (xsb + m1 - 2.f * acc[t][u][3]) * OUT_SCALE;
            *(float2*)(o0 + col) = v0;
            *(float2*)(o1 + col) = v1;
        }
    }
}

// ---------------------------------------------------------------------------
// Launch
// ---------------------------------------------------------------------------
extern "C" void kernel_launch(void* const* d_in, const int* in_sizes, int n_in,
                              void* d_out, int out_size) {
    (void)n_in; (void)out_size;
    const float* X = (const float*)d_in[0];   // observation        [4096, 2496]
    const float* M = (const float*)d_in[1];   // observation_matrix [2048, 2496]
    if (in_sizes[0] == S_ROWS * D_DIM) {      // robust to ordering
        X = (const float*)d_in[1];
        M = (const float*)d_in[0];
    }
    float* out = (float*)d_out;

    cudaFuncSetAttribute(gemm_kernel,
                         cudaFuncAttributeMaxDynamicSharedMemorySize, SMEM_BYTES);

    convert_all_kernel<<<B_ROWS + S_ROWS, 256>>>(X, M);

    dim3 grid(S_ROWS / BN, B_ROWS / BM);  // (8, 32) = 256 CTAs
    gemm_kernel<<<grid, 256, SMEM_BYTES>>>(out);
}